// round 1
// baseline (speedup 1.0000x reference)
#include <cuda_runtime.h>
#include <math.h>

#define NTOK 4096
#define DIM  1024
#define FF   4096
#define NEXP 32
#define TOPK 2
#define CAP  512

// ---------------- scratch (static device allocations are allowed) ----------
__device__ float g_h[(size_t)NEXP * CAP * FF];    // 256 MB: gelu(fc1) activations
__device__ float g_yo[(size_t)NEXP * CAP * DIM];  // 64 MB: fc2 outputs per slot
__device__ int   g_slot_token[NEXP * CAP];        // slot -> token index
__device__ int   g_pair_slot[NTOK * TOPK];        // pair -> e*CAP+pos, or -1 dropped
__device__ float g_pair_w[NTOK * TOPK];           // pair combine weight
__device__ int   g_topi[NTOK * TOPK];             // pair expert id (ordered)
__device__ int   g_nused[NEXP];                   // rows actually used per expert

// ---------------- gating: logits -> top2 -> renormalized weights ----------
// top2-of-softmax == top2-of-logits; renormalized weights = sigmoid(l0-l1).
__global__ void gate_kernel(const float* __restrict__ x,
                            const float* __restrict__ gw,
                            const float* __restrict__ gb) {
    int warp = (blockIdx.x * blockDim.x + threadIdx.x) >> 5;
    int lane = threadIdx.x & 31;
    if (warp >= NTOK) return;

    const float4* xr = (const float4*)(x + (size_t)warp * DIM);
    float4 xv[8];
#pragma unroll
    for (int j = 0; j < 8; j++) xv[j] = xr[j * 32 + lane];

    float mylogit = 0.0f;  // logit of expert == lane
    for (int e = 0; e < NEXP; e++) {
        const float4* wr = (const float4*)(gw + (size_t)e * DIM);
        float s = 0.0f;
#pragma unroll
        for (int j = 0; j < 8; j++) {
            float4 wv = wr[j * 32 + lane];
            s += xv[j].x * wv.x + xv[j].y * wv.y + xv[j].z * wv.z + xv[j].w * wv.w;
        }
#pragma unroll
        for (int o = 16; o > 0; o >>= 1) s += __shfl_xor_sync(0xffffffffu, s, o);
        if (lane == e) mylogit = s + gb[e];
    }

    // top-1 (lowest index wins ties, matching top_k)
    float m0 = mylogit; int i0 = lane;
#pragma unroll
    for (int o = 16; o > 0; o >>= 1) {
        float ov = __shfl_xor_sync(0xffffffffu, m0, o);
        int   oi = __shfl_xor_sync(0xffffffffu, i0, o);
        if (ov > m0 || (ov == m0 && oi < i0)) { m0 = ov; i0 = oi; }
    }
    // top-2
    float v2 = (lane == i0) ? -INFINITY : mylogit;
    float m1 = v2; int i1 = lane;
#pragma unroll
    for (int o = 16; o > 0; o >>= 1) {
        float ov = __shfl_xor_sync(0xffffffffu, m1, o);
        int   oi = __shfl_xor_sync(0xffffffffu, i1, o);
        if (ov > m1 || (ov == m1 && oi < i1)) { m1 = ov; i1 = oi; }
    }
    if (lane == 0) {
        float w0 = 1.0f / (1.0f + expf(m1 - m0));
        g_topi[warp * 2 + 0] = i0;
        g_topi[warp * 2 + 1] = i1;
        g_pair_w[warp * 2 + 0] = w0;
        g_pair_w[warp * 2 + 1] = 1.0f - w0;
    }
}

// ---------------- ordered capacity scan (one warp, lane == expert) --------
__global__ void scan_kernel() {
    int lane = threadIdx.x;
    int cnt = 0;
    for (int i = 0; i < NTOK * TOPK; i++) {
        int e = g_topi[i];
        if (e == lane) {
            int pos = cnt++;
            if (pos < CAP) {
                g_pair_slot[i] = e * CAP + pos;
                g_slot_token[e * CAP + pos] = i >> 1;
            } else {
                g_pair_slot[i] = -1;
            }
        }
    }
    g_nused[lane] = min(cnt, CAP);
}

__device__ __forceinline__ float gelu_tanh(float v) {
    float c = v + 0.044715f * v * v * v;
    return 0.5f * v * (1.0f + tanhf(0.7978845608028654f * c));
}

// ---------------- GEMM1: h = gelu(gather(x) @ w1[e]^T + b1[e]) ------------
// A: [CAP, DIM] gathered rows of x (K-major). B: w1[e] [FF, DIM] (K-major).
__global__ __launch_bounds__(256) void gemm1_kernel(const float* __restrict__ x,
                                                    const float* __restrict__ w1,
                                                    const float* __restrict__ b1) {
    const int e = blockIdx.z;
    const int nu = g_nused[e];
    const int row0 = blockIdx.y * 128;
    if (row0 >= nu) return;
    const int col0 = blockIdx.x * 128;

    __shared__ float As[8][132];
    __shared__ float Bs[8][132];
    __shared__ int   tok[128];

    const int tid = threadIdx.x;
    if (tid < 128) {
        int c = row0 + tid;
        tok[tid] = (c < nu) ? g_slot_token[e * CAP + c] : 0;
    }
    __syncthreads();

    float acc[8][8];
#pragma unroll
    for (int i = 0; i < 8; i++)
#pragma unroll
        for (int j = 0; j < 8; j++) acc[i][j] = 0.0f;

    const int tx = tid & 15, ty = tid >> 4;
    const int lrow = tid >> 1;
    const int lcol = (tid & 1) * 4;

    const float* a_ptr = x + (size_t)tok[lrow] * DIM + lcol;
    const float* b_ptr = w1 + (size_t)e * FF * DIM + (size_t)(col0 + lrow) * DIM + lcol;

    for (int k0 = 0; k0 < DIM; k0 += 8) {
        float4 av = *(const float4*)(a_ptr + k0);
        float4 bv = *(const float4*)(b_ptr + k0);
        As[lcol + 0][lrow] = av.x; As[lcol + 1][lrow] = av.y;
        As[lcol + 2][lrow] = av.z; As[lcol + 3][lrow] = av.w;
        Bs[lcol + 0][lrow] = bv.x; Bs[lcol + 1][lrow] = bv.y;
        Bs[lcol + 2][lrow] = bv.z; Bs[lcol + 3][lrow] = bv.w;
        __syncthreads();
#pragma unroll
        for (int k = 0; k < 8; k++) {
            float4 a0 = *(const float4*)&As[k][ty * 4];
            float4 a1 = *(const float4*)&As[k][64 + ty * 4];
            float4 b0 = *(const float4*)&Bs[k][tx * 4];
            float4 b1v = *(const float4*)&Bs[k][64 + tx * 4];
            float a[8] = {a0.x, a0.y, a0.z, a0.w, a1.x, a1.y, a1.z, a1.w};
            float b[8] = {b0.x, b0.y, b0.z, b0.w, b1v.x, b1v.y, b1v.z, b1v.w};
#pragma unroll
            for (int i = 0; i < 8; i++)
#pragma unroll
                for (int j = 0; j < 8; j++) acc[i][j] += a[i] * b[j];
        }
        __syncthreads();
    }

    float* hb = g_h + ((size_t)e * CAP + row0) * FF + col0;
    const float* bb = b1 + (size_t)e * FF + col0;
#pragma unroll
    for (int i = 0; i < 8; i++) {
        int r = ty * 4 + (i & 3) + ((i >= 4) ? 64 : 0);
#pragma unroll
        for (int j = 0; j < 8; j++) {
            int cc = tx * 4 + (j & 3) + ((j >= 4) ? 64 : 0);
            hb[(size_t)r * FF + cc] = gelu_tanh(acc[i][j] + bb[cc]);
        }
    }
}

// ---------------- GEMM2: yo = h @ w2[e] + b2[e] ---------------------------
// A: g_h[e] [CAP, FF] (K-major). B: w2[e] [FF, DIM] (k rows, n cols).
__global__ __launch_bounds__(256) void gemm2_kernel(const float* __restrict__ w2,
                                                    const float* __restrict__ b2) {
    const int e = blockIdx.z;
    const int nu = g_nused[e];
    const int row0 = blockIdx.y * 128;
    if (row0 >= nu) return;
    const int col0 = blockIdx.x * 128;

    __shared__ float As[8][132];
    __shared__ float Bs[8][132];

    const int tid = threadIdx.x;
    const int tx = tid & 15, ty = tid >> 4;
    const int lrow = tid >> 1;
    const int lcol = (tid & 1) * 4;
    const int bk = tid >> 5;         // 0..7
    const int bn = (tid & 31) * 4;   // 0..124

    float acc[8][8];
#pragma unroll
    for (int i = 0; i < 8; i++)
#pragma unroll
        for (int j = 0; j < 8; j++) acc[i][j] = 0.0f;

    const float* a_ptr = g_h + ((size_t)e * CAP + row0 + lrow) * FF + lcol;
    const float* b_ptr = w2 + (size_t)e * FF * DIM + (size_t)bk * DIM + col0 + bn;

    for (int k0 = 0; k0 < FF; k0 += 8) {
        float4 av = *(const float4*)(a_ptr + k0);
        float4 bv = *(const float4*)(b_ptr + (size_t)k0 * DIM);
        As[lcol + 0][lrow] = av.x; As[lcol + 1][lrow] = av.y;
        As[lcol + 2][lrow] = av.z; As[lcol + 3][lrow] = av.w;
        *(float4*)&Bs[bk][bn] = bv;
        __syncthreads();
#pragma unroll
        for (int k = 0; k < 8; k++) {
            float4 a0 = *(const float4*)&As[k][ty * 4];
            float4 a1 = *(const float4*)&As[k][64 + ty * 4];
            float4 b0 = *(const float4*)&Bs[k][tx * 4];
            float4 b1v = *(const float4*)&Bs[k][64 + tx * 4];
            float a[8] = {a0.x, a0.y, a0.z, a0.w, a1.x, a1.y, a1.z, a1.w};
            float b[8] = {b0.x, b0.y, b0.z, b0.w, b1v.x, b1v.y, b1v.z, b1v.w};
#pragma unroll
            for (int i = 0; i < 8; i++)
#pragma unroll
                for (int j = 0; j < 8; j++) acc[i][j] += a[i] * b[j];
        }
        __syncthreads();
    }

    float* yb = g_yo + ((size_t)e * CAP + row0) * DIM + col0;
    const float* bb = b2 + (size_t)e * DIM + col0;
#pragma unroll
    for (int i = 0; i < 8; i++) {
        int r = ty * 4 + (i & 3) + ((i >= 4) ? 64 : 0);
#pragma unroll
        for (int j = 0; j < 8; j++) {
            int cc = tx * 4 + (j & 3) + ((j >= 4) ? 64 : 0);
            yb[(size_t)r * DIM + cc] = acc[i][j] + bb[cc];
        }
    }
}

// ---------------- combine: out[t] = sum_k w_k * yo[slot_k] ----------------
__global__ void combine_kernel(float* __restrict__ out) {
    int t = blockIdx.x;
    int d = threadIdx.x * 4;
    int s0 = g_pair_slot[2 * t + 0];
    int s1 = g_pair_slot[2 * t + 1];
    float w0 = g_pair_w[2 * t + 0];
    float w1v = g_pair_w[2 * t + 1];
    float4 r = make_float4(0.f, 0.f, 0.f, 0.f);
    if (s0 >= 0) {
        float4 a = *(const float4*)(g_yo + (size_t)s0 * DIM + d);
        r.x += w0 * a.x; r.y += w0 * a.y; r.z += w0 * a.z; r.w += w0 * a.w;
    }
    if (s1 >= 0) {
        float4 a = *(const float4*)(g_yo + (size_t)s1 * DIM + d);
        r.x += w1v * a.x; r.y += w1v * a.y; r.z += w1v * a.z; r.w += w1v * a.w;
    }
    *(float4*)(out + (size_t)t * DIM + d) = r;
}

// ---------------- launch --------------------------------------------------
extern "C" void kernel_launch(void* const* d_in, const int* in_sizes, int n_in,
                              void* d_out, int out_size) {
    const float* x      = (const float*)d_in[0];
    const float* gate_w = (const float*)d_in[1];
    const float* gate_b = (const float*)d_in[2];
    const float* w1     = (const float*)d_in[3];
    const float* b1     = (const float*)d_in[4];
    const float* w2     = (const float*)d_in[5];
    const float* b2     = (const float*)d_in[6];
    float* out = (float*)d_out;

    gate_kernel<<<NTOK / 8, 256>>>(x, gate_w, gate_b);
    scan_kernel<<<1, 32>>>();
    gemm1_kernel<<<dim3(FF / 128, CAP / 128, NEXP), 256>>>(x, w1, b1);
    gemm2_kernel<<<dim3(DIM / 128, CAP / 128, NEXP), 256>>>(w2, b2);
    combine_kernel<<<NTOK, 256>>>(out);
}

// round 3
// speedup vs baseline: 2.3810x; 2.3810x over previous
#include <cuda_runtime.h>
#include <cuda_bf16.h>
#include <math.h>
#include <stdint.h>

#define NTOK 4096
#define DIM  1024
#define FF   4096
#define NEXP 32
#define TOPK 2
#define CAP  512

// g_h: gelu(fc1) pre-split bf16 hi/lo in GEMM2 A layout:
// row = e*CAP+slot (8192 bf16): per 16-fp32 group g: elems [g*32 .. g*32+15] = hi,
// [g*32+16 .. g*32+31] = lo.
__device__ __nv_bfloat16 g_h[(size_t)NEXP * CAP * FF * 2];
__device__ float g_yo[(size_t)NEXP * CAP * DIM];
__device__ int   g_slot_token[NEXP * CAP];
__device__ int   g_pair_slot[NTOK * TOPK];
__device__ float g_pair_w[NTOK * TOPK];
__device__ int   g_topi[NTOK * TOPK];
__device__ int   g_nused[NEXP];

// ---------------- helpers ----------------
__device__ __forceinline__ uint32_t smem_u32(const void* p) {
    uint32_t a;
    asm("{ .reg .u64 t; cvta.to.shared.u64 t, %1; cvt.u32.u64 %0, t; }" : "=r"(a) : "l"(p));
    return a;
}
__device__ __forceinline__ void ldsm_x4(uint32_t& r0, uint32_t& r1, uint32_t& r2, uint32_t& r3,
                                        uint32_t addr) {
    asm volatile("ldmatrix.sync.aligned.m8n8.x4.shared.b16 {%0,%1,%2,%3}, [%4];"
                 : "=r"(r0), "=r"(r1), "=r"(r2), "=r"(r3) : "r"(addr));
}
__device__ __forceinline__ void ldsm_x2(uint32_t& r0, uint32_t& r1, uint32_t addr) {
    asm volatile("ldmatrix.sync.aligned.m8n8.x2.shared.b16 {%0,%1}, [%2];"
                 : "=r"(r0), "=r"(r1) : "r"(addr));
}
__device__ __forceinline__ void mma16816(float* c, uint32_t a0, uint32_t a1, uint32_t a2,
                                         uint32_t a3, uint32_t b0, uint32_t b1) {
    asm volatile(
        "mma.sync.aligned.m16n8k16.row.col.f32.bf16.bf16.f32 "
        "{%0,%1,%2,%3}, {%4,%5,%6,%7}, {%8,%9}, {%0,%1,%2,%3};"
        : "+f"(c[0]), "+f"(c[1]), "+f"(c[2]), "+f"(c[3])
        : "r"(a0), "r"(a1), "r"(a2), "r"(a3), "r"(b0), "r"(b1));
}
__device__ __forceinline__ uint32_t pk(__nv_bfloat16 a, __nv_bfloat16 b) {
    return (uint32_t)__bfloat16_as_ushort(a) | ((uint32_t)__bfloat16_as_ushort(b) << 16);
}
// split 8 fp32 -> hi uint4 (8 bf16) + lo uint4
__device__ __forceinline__ void split8(float4 v0, float4 v1, uint4& hi, uint4& lo) {
    float f[8] = {v0.x, v0.y, v0.z, v0.w, v1.x, v1.y, v1.z, v1.w};
    __nv_bfloat16 h[8], l[8];
#pragma unroll
    for (int i = 0; i < 8; i++) {
        h[i] = __float2bfloat16(f[i]);
        l[i] = __float2bfloat16(f[i] - __bfloat162float(h[i]));
    }
    hi = make_uint4(pk(h[0], h[1]), pk(h[2], h[3]), pk(h[4], h[5]), pk(h[6], h[7]));
    lo = make_uint4(pk(l[0], l[1]), pk(l[2], l[3]), pk(l[4], l[5]), pk(l[6], l[7]));
}
__device__ __forceinline__ float gelu_tanh(float v) {
    float c = v + 0.044715f * v * v * v;
    return 0.5f * v * (1.0f + tanhf(0.7978845608028654f * c));
}

// smem tile: 128 rows x (16 hi + 16 lo bf16) , row stride 40 elems = 80 bytes
#define ROWB 80
#define TILEB (128 * ROWB)   // 10240 bytes per buffer

// ---------------- gating ----------------
__global__ void gate_kernel(const float* __restrict__ x, const float* __restrict__ gw,
                            const float* __restrict__ gb) {
    int warp = (blockIdx.x * blockDim.x + threadIdx.x) >> 5;
    int lane = threadIdx.x & 31;
    if (warp >= NTOK) return;
    const float4* xr = (const float4*)(x + (size_t)warp * DIM);
    float4 xv[8];
#pragma unroll
    for (int j = 0; j < 8; j++) xv[j] = xr[j * 32 + lane];
    float mylogit = 0.0f;
    for (int e = 0; e < NEXP; e++) {
        const float4* wr = (const float4*)(gw + (size_t)e * DIM);
        float s = 0.0f;
#pragma unroll
        for (int j = 0; j < 8; j++) {
            float4 wv = wr[j * 32 + lane];
            s += xv[j].x * wv.x + xv[j].y * wv.y + xv[j].z * wv.z + xv[j].w * wv.w;
        }
#pragma unroll
        for (int o = 16; o > 0; o >>= 1) s += __shfl_xor_sync(0xffffffffu, s, o);
        if (lane == e) mylogit = s + gb[e];
    }
    float m0 = mylogit; int i0 = lane;
#pragma unroll
    for (int o = 16; o > 0; o >>= 1) {
        float ov = __shfl_xor_sync(0xffffffffu, m0, o);
        int   oi = __shfl_xor_sync(0xffffffffu, i0, o);
        if (ov > m0 || (ov == m0 && oi < i0)) { m0 = ov; i0 = oi; }
    }
    float v2 = (lane == i0) ? -INFINITY : mylogit;
    float m1 = v2; int i1 = lane;
#pragma unroll
    for (int o = 16; o > 0; o >>= 1) {
        float ov = __shfl_xor_sync(0xffffffffu, m1, o);
        int   oi = __shfl_xor_sync(0xffffffffu, i1, o);
        if (ov > m1 || (ov == m1 && oi < i1)) { m1 = ov; i1 = oi; }
    }
    if (lane == 0) {
        float w0 = 1.0f / (1.0f + expf(m1 - m0));
        g_topi[warp * 2 + 0] = i0;
        g_topi[warp * 2 + 1] = i1;
        g_pair_w[warp * 2 + 0] = w0;
        g_pair_w[warp * 2 + 1] = 1.0f - w0;
    }
}

// ---------------- ordered capacity scan ----------------
__global__ void scan_kernel() {
    int lane = threadIdx.x;
    int cnt = 0;
    for (int i = 0; i < NTOK * TOPK; i++) {
        int e = g_topi[i];
        if (e == lane) {
            int pos = cnt++;
            if (pos < CAP) {
                g_pair_slot[i] = e * CAP + pos;
                g_slot_token[e * CAP + pos] = i >> 1;
            } else {
                g_pair_slot[i] = -1;
            }
        }
    }
    g_nused[lane] = min(cnt, CAP);
}

// ---------------- compute core (shared by both GEMMs) ----------------
// acc: float[2][8][4]; warp tile 32(m) x 64(n); smem buffers at sA/sB (u32 smem addrs)
__device__ __forceinline__ void compute_iter(uint32_t sA, uint32_t sB, int m0, int n0, int lane,
                                             float acc[2][8][4]) {
    uint32_t bh[8][2], bl[8][2];
    const uint32_t brow = (uint32_t)(n0 + (lane & 7)) * ROWB + (((lane >> 3) & 1) * 16);
#pragma unroll
    for (int nj = 0; nj < 8; nj++) {
        uint32_t ba = sB + brow + nj * 8 * ROWB;
        ldsm_x2(bh[nj][0], bh[nj][1], ba);
        ldsm_x2(bl[nj][0], bl[nj][1], ba + 32);
    }
    const uint32_t arow = (uint32_t)(m0 + (lane & 15)) * ROWB + ((lane >> 4) * 16);
#pragma unroll
    for (int mi = 0; mi < 2; mi++) {
        uint32_t ah0, ah1, ah2, ah3, al0, al1, al2, al3;
        uint32_t aa = sA + arow + mi * 16 * ROWB;
        ldsm_x4(ah0, ah1, ah2, ah3, aa);
        ldsm_x4(al0, al1, al2, al3, aa + 32);
#pragma unroll
        for (int nj = 0; nj < 8; nj++) {
            mma16816(acc[mi][nj], ah0, ah1, ah2, ah3, bh[nj][0], bh[nj][1]);
            mma16816(acc[mi][nj], ah0, ah1, ah2, ah3, bl[nj][0], bl[nj][1]);
            mma16816(acc[mi][nj], al0, al1, al2, al3, bh[nj][0], bh[nj][1]);
        }
    }
}

// ---------------- GEMM1: h = gelu(gather(x) @ w1[e]^T + b1) ----------------
__global__ __launch_bounds__(256, 1) void gemm1_kernel(const float* __restrict__ x,
                                                       const float* __restrict__ w1,
                                                       const float* __restrict__ b1) {
    const int e = blockIdx.z;
    const int nu = g_nused[e];
    const int row0 = blockIdx.y * 128;
    if (row0 >= nu) return;
    const int col0 = blockIdx.x * 128;

    __shared__ __align__(16) char sAb[2 * TILEB];
    __shared__ __align__(16) char sBb[2 * TILEB];
    __shared__ int tok[128];

    const int tid = threadIdx.x;
    const int lane = tid & 31, wid = tid >> 5;
    const int m0 = (wid & 3) * 32, n0 = (wid >> 2) * 64;

    if (tid < 128) {
        int c = row0 + tid;
        tok[tid] = (c < nu) ? g_slot_token[e * CAP + c] : 0;
    }
    __syncthreads();

    const uint32_t sA0 = smem_u32(sAb), sB0 = smem_u32(sBb);
    const int r = tid >> 1, half = tid & 1;
    const float* ap = x + (size_t)tok[r] * DIM + half * 8;
    const float* bp = w1 + (size_t)e * FF * DIM + (size_t)(col0 + r) * DIM + half * 8;
    char* stA = sAb + r * ROWB + half * 16;   // hi at +0, lo at +32
    char* stB = sBb + r * ROWB + half * 16;

    float acc[2][8][4];
#pragma unroll
    for (int i = 0; i < 2; i++)
#pragma unroll
        for (int j = 0; j < 8; j++)
#pragma unroll
            for (int q = 0; q < 4; q++) acc[i][j][q] = 0.0f;

    // prologue fill stage 0
    {
        float4 a0 = *(const float4*)(ap), a1 = *(const float4*)(ap + 4);
        float4 b0 = *(const float4*)(bp), b1v = *(const float4*)(bp + 4);
        uint4 hi, lo;
        split8(a0, a1, hi, lo);
        *(uint4*)(stA) = hi; *(uint4*)(stA + 32) = lo;
        split8(b0, b1v, hi, lo);
        *(uint4*)(stB) = hi; *(uint4*)(stB + 32) = lo;
    }
    __syncthreads();

    const int NIT = DIM / 16;
    for (int it = 0; it < NIT; ++it) {
        float4 a0, a1, b0, b1v;
        if (it + 1 < NIT) {
            const float* a = ap + (it + 1) * 16;
            const float* b = bp + (it + 1) * 16;
            a0 = *(const float4*)(a); a1 = *(const float4*)(a + 4);
            b0 = *(const float4*)(b); b1v = *(const float4*)(b + 4);
        }
        const int s = it & 1;
        compute_iter(sA0 + s * TILEB, sB0 + s * TILEB, m0, n0, lane, acc);
        if (it + 1 < NIT) {
            const int ns = s ^ 1;
            uint4 hi, lo;
            split8(a0, a1, hi, lo);
            *(uint4*)(stA + ns * TILEB) = hi; *(uint4*)(stA + ns * TILEB + 32) = lo;
            split8(b0, b1v, hi, lo);
            *(uint4*)(stB + ns * TILEB) = hi; *(uint4*)(stB + ns * TILEB + 32) = lo;
        }
        __syncthreads();
    }

    // epilogue: bias + gelu + hi/lo split -> g_h
    const int rbase = lane >> 2, cbase = (lane & 3) * 2;
#pragma unroll
    for (int mi = 0; mi < 2; mi++) {
#pragma unroll
        for (int nj = 0; nj < 8; nj++) {
#pragma unroll
            for (int hrow = 0; hrow < 2; hrow++) {
                int rl = m0 + mi * 16 + rbase + hrow * 8;
                int f = col0 + n0 + nj * 8 + cbase;
                float v0 = acc[mi][nj][hrow * 2 + 0] + b1[e * FF + f];
                float v1 = acc[mi][nj][hrow * 2 + 1] + b1[e * FF + f + 1];
                v0 = gelu_tanh(v0); v1 = gelu_tanh(v1);
                __nv_bfloat16 h0 = __float2bfloat16(v0), h1 = __float2bfloat16(v1);
                __nv_bfloat16 l0 = __float2bfloat16(v0 - __bfloat162float(h0));
                __nv_bfloat16 l1 = __float2bfloat16(v1 - __bfloat162float(h1));
                __nv_bfloat16* hr =
                    g_h + (size_t)(e * CAP + row0 + rl) * (FF * 2) + (f >> 4) * 32 + (f & 15);
                *(uint32_t*)hr = pk(h0, h1);
                *(uint32_t*)(hr + 16) = pk(l0, l1);
            }
        }
    }
}

// ---------------- GEMM2: yo = h @ w2[e] + b2 ----------------
__global__ __launch_bounds__(256, 1) void gemm2_kernel(const float* __restrict__ w2,
                                                       const float* __restrict__ b2) {
    const int e = blockIdx.z;
    const int nu = g_nused[e];
    const int row0 = blockIdx.y * 128;
    if (row0 >= nu) return;
    const int col0 = blockIdx.x * 128;

    __shared__ __align__(16) char sAb[2 * TILEB];
    __shared__ __align__(16) char sBb[2 * TILEB];

    const int tid = threadIdx.x;
    const int lane = tid & 31, wid = tid >> 5;
    const int m0 = (wid & 3) * 32, n0 = (wid >> 2) * 64;

    const uint32_t sA0 = smem_u32(sAb), sB0 = smem_u32(sBb);
    // A: straight copy of pre-split rows from g_h
    const int r = tid >> 1, half = tid & 1;
    const __nv_bfloat16* asrc = g_h + (size_t)(e * CAP + row0 + r) * (FF * 2) + half * 16;
    char* stA = sAb + r * ROWB + half * 32;  // 32B per thread (16 bf16)
    // B: transpose w2[k][n] -> Bs[n][k], hi/lo split
    const int bn = tid & 127, kseg = tid >> 7;
    const float* bsrc = w2 + (size_t)e * FF * DIM + col0 + bn + (size_t)kseg * 8 * DIM;
    char* stB = sBb + bn * ROWB + kseg * 16;

    float acc[2][8][4];
#pragma unroll
    for (int i = 0; i < 2; i++)
#pragma unroll
        for (int j = 0; j < 8; j++)
#pragma unroll
            for (int q = 0; q < 4; q++) acc[i][j][q] = 0.0f;

    // prologue
    {
        uint4 c0 = *(const uint4*)(asrc), c1 = *(const uint4*)(asrc + 8);
        *(uint4*)(stA) = c0; *(uint4*)(stA + 16) = c1;
        float f[8];
#pragma unroll
        for (int j = 0; j < 8; j++) f[j] = bsrc[(size_t)j * DIM];
        uint4 hi, lo;
        split8(make_float4(f[0], f[1], f[2], f[3]), make_float4(f[4], f[5], f[6], f[7]), hi, lo);
        *(uint4*)(stB) = hi; *(uint4*)(stB + 32) = lo;
    }
    __syncthreads();

    const int NIT = FF / 16;
    for (int it = 0; it < NIT; ++it) {
        uint4 c0, c1; float f[8];
        if (it + 1 < NIT) {
            const __nv_bfloat16* a = asrc + (size_t)(it + 1) * 32;
            c0 = *(const uint4*)(a); c1 = *(const uint4*)(a + 8);
            const float* b = bsrc + (size_t)(it + 1) * 16 * DIM;
#pragma unroll
            for (int j = 0; j < 8; j++) f[j] = b[(size_t)j * DIM];
        }
        const int s = it & 1;
        compute_iter(sA0 + s * TILEB, sB0 + s * TILEB, m0, n0, lane, acc);
        if (it + 1 < NIT) {
            const int ns = s ^ 1;
            *(uint4*)(stA + ns * TILEB) = c0; *(uint4*)(stA + ns * TILEB + 16) = c1;
            uint4 hi, lo;
            split8(make_float4(f[0], f[1], f[2], f[3]), make_float4(f[4], f[5], f[6], f[7]), hi, lo);
            *(uint4*)(stB + ns * TILEB) = hi; *(uint4*)(stB + ns * TILEB + 32) = lo;
        }
        __syncthreads();
    }

    // epilogue: bias -> g_yo (fp32)
    const int rbase = lane >> 2, cbase = (lane & 3) * 2;
#pragma unroll
    for (int mi = 0; mi < 2; mi++) {
#pragma unroll
        for (int nj = 0; nj < 8; nj++) {
#pragma unroll
            for (int hrow = 0; hrow < 2; hrow++) {
                int rl = m0 + mi * 16 + rbase + hrow * 8;
                int d = col0 + n0 + nj * 8 + cbase;
                float v0 = acc[mi][nj][hrow * 2 + 0] + b2[e * DIM + d];
                float v1 = acc[mi][nj][hrow * 2 + 1] + b2[e * DIM + d + 1];
                float* dst = g_yo + (size_t)(e * CAP + row0 + rl) * DIM + d;
                *(float2*)dst = make_float2(v0, v1);
            }
        }
    }
}

// ---------------- combine ----------------
__global__ void combine_kernel(float* __restrict__ out) {
    int t = blockIdx.x;
    int d = threadIdx.x * 4;
    int s0 = g_pair_slot[2 * t + 0];
    int s1 = g_pair_slot[2 * t + 1];
    float w0 = g_pair_w[2 * t + 0];
    float w1v = g_pair_w[2 * t + 1];
    float4 r = make_float4(0.f, 0.f, 0.f, 0.f);
    if (s0 >= 0) {
        float4 a = *(const float4*)(g_yo + (size_t)s0 * DIM + d);
        r.x += w0 * a.x; r.y += w0 * a.y; r.z += w0 * a.z; r.w += w0 * a.w;
    }
    if (s1 >= 0) {
        float4 a = *(const float4*)(g_yo + (size_t)s1 * DIM + d);
        r.x += w1v * a.x; r.y += w1v * a.y; r.z += w1v * a.z; r.w += w1v * a.w;
    }
    *(float4*)(out + (size_t)t * DIM + d) = r;
}

// ---------------- launch ----------------
extern "C" void kernel_launch(void* const* d_in, const int* in_sizes, int n_in,
                              void* d_out, int out_size) {
    const float* x      = (const float*)d_in[0];
    const float* gate_w = (const float*)d_in[1];
    const float* gate_b = (const float*)d_in[2];
    const float* w1     = (const float*)d_in[3];
    const float* b1     = (const float*)d_in[4];
    const float* w2     = (const float*)d_in[5];
    const float* b2     = (const float*)d_in[6];
    float* out = (float*)d_out;

    gate_kernel<<<NTOK / 8, 256>>>(x, gate_w, gate_b);
    scan_kernel<<<1, 32>>>();
    gemm1_kernel<<<dim3(FF / 128, CAP / 128, NEXP), 256>>>(x, w1, b1);
    gemm2_kernel<<<dim3(DIM / 128, CAP / 128, NEXP), 256>>>(w2, b2);
    combine_kernel<<<NTOK, 256>>>(out);
}

// round 4
// speedup vs baseline: 2.6060x; 1.0945x over previous
#include <cuda_runtime.h>
#include <cuda_bf16.h>
#include <math.h>
#include <stdint.h>

#define NTOK 4096
#define DIM  1024
#define FF   4096
#define NEXP 32
#define TOPK 2
#define CAP  512

// bf16 hi/lo "group" layout: per 16 fp32 values -> 64B block [16 hi bf16][16 lo bf16]
__device__ __nv_bfloat16 g_xb [(size_t)NTOK * DIM * 2];            // 16 MB
__device__ __nv_bfloat16 g_w1b[(size_t)NEXP * FF * DIM * 2];       // 512 MB
__device__ __nv_bfloat16 g_w2b[(size_t)NEXP * DIM * FF * 2];       // 512 MB (transposed)
__device__ __nv_bfloat16 g_h  [(size_t)NEXP * CAP * FF * 2];       // 256 MB
__device__ float g_yo[(size_t)NEXP * CAP * DIM];                   // 64 MB
__device__ int   g_slot_token[NEXP * CAP];
__device__ int   g_pair_slot[NTOK * TOPK];
__device__ float g_pair_w[NTOK * TOPK];
__device__ int   g_topi[NTOK * TOPK];
__device__ int   g_nused[NEXP];

// ---------------- helpers ----------------
__device__ __forceinline__ uint32_t smem_u32(const void* p) {
    uint32_t a;
    asm("{ .reg .u64 t; cvta.to.shared.u64 t, %1; cvt.u32.u64 %0, t; }" : "=r"(a) : "l"(p));
    return a;
}
__device__ __forceinline__ void cp16(uint32_t d, const void* s) {
    asm volatile("cp.async.cg.shared.global [%0], [%1], 16;" :: "r"(d), "l"(s));
}
__device__ __forceinline__ void cp_commit() { asm volatile("cp.async.commit_group;"); }
template <int N>
__device__ __forceinline__ void cp_wait() { asm volatile("cp.async.wait_group %0;" :: "n"(N)); }

__device__ __forceinline__ void ldsm_x4(uint32_t& r0, uint32_t& r1, uint32_t& r2, uint32_t& r3,
                                        uint32_t addr) {
    asm volatile("ldmatrix.sync.aligned.m8n8.x4.shared.b16 {%0,%1,%2,%3}, [%4];"
                 : "=r"(r0), "=r"(r1), "=r"(r2), "=r"(r3) : "r"(addr));
}
__device__ __forceinline__ void ldsm_x2(uint32_t& r0, uint32_t& r1, uint32_t addr) {
    asm volatile("ldmatrix.sync.aligned.m8n8.x2.shared.b16 {%0,%1}, [%2];"
                 : "=r"(r0), "=r"(r1) : "r"(addr));
}
__device__ __forceinline__ void mma16816(float* c, uint32_t a0, uint32_t a1, uint32_t a2,
                                         uint32_t a3, uint32_t b0, uint32_t b1) {
    asm volatile(
        "mma.sync.aligned.m16n8k16.row.col.f32.bf16.bf16.f32 "
        "{%0,%1,%2,%3}, {%4,%5,%6,%7}, {%8,%9}, {%0,%1,%2,%3};"
        : "+f"(c[0]), "+f"(c[1]), "+f"(c[2]), "+f"(c[3])
        : "r"(a0), "r"(a1), "r"(a2), "r"(a3), "r"(b0), "r"(b1));
}
__device__ __forceinline__ uint32_t pk(__nv_bfloat16 a, __nv_bfloat16 b) {
    return (uint32_t)__bfloat16_as_ushort(a) | ((uint32_t)__bfloat16_as_ushort(b) << 16);
}
__device__ __forceinline__ void split8(float4 v0, float4 v1, uint4& hi, uint4& lo) {
    float f[8] = {v0.x, v0.y, v0.z, v0.w, v1.x, v1.y, v1.z, v1.w};
    __nv_bfloat16 h[8], l[8];
#pragma unroll
    for (int i = 0; i < 8; i++) {
        h[i] = __float2bfloat16(f[i]);
        l[i] = __float2bfloat16(f[i] - __bfloat162float(h[i]));
    }
    hi = make_uint4(pk(h[0], h[1]), pk(h[2], h[3]), pk(h[4], h[5]), pk(h[6], h[7]));
    lo = make_uint4(pk(l[0], l[1]), pk(l[2], l[3]), pk(l[4], l[5]), pk(l[6], l[7]));
}
__device__ __forceinline__ float gelu_tanh(float v) {
    float c = v + 0.044715f * v * v * v;
    return 0.5f * v * (1.0f + tanhf(0.7978845608028654f * c));
}

#define ROWB   80          // smem row stride (64B data + 16B pad; conflict-free ldsm)
#define TILEB  (128 * ROWB)
#define STAGES 4
#define SMEMB  (2 * STAGES * TILEB + 512)

// ---------------- conversion kernels ----------------
__global__ __launch_bounds__(256) void conv_split_kernel(const float* __restrict__ src,
                                                         __nv_bfloat16* __restrict__ dst,
                                                         int ngroups) {
    int i = blockIdx.x * 256 + threadIdx.x;
    if (i >= ngroups) return;
    const float4* s = (const float4*)(src + (size_t)i * 16);
    float4 v0 = s[0], v1 = s[1], v2 = s[2], v3 = s[3];
    uint4 h0, l0, h1, l1;
    split8(v0, v1, h0, l0);
    split8(v2, v3, h1, l1);
    uint4* d = (uint4*)(dst + (size_t)i * 32);
    d[0] = h0; d[1] = h1; d[2] = l0; d[3] = l1;
}

// transpose w2[e][f][d] -> g_w2b[e][d] rows over k=f, with hi/lo split
__global__ __launch_bounds__(256) void conv_w2t_kernel(const float* __restrict__ w2) {
    const int e = blockIdx.z;
    const int f0 = blockIdx.x * 64;
    const int d0 = blockIdx.y * 64;
    __shared__ float s[64][65];
    const int tid = threadIdx.x;
    {
        int fr = tid >> 2, part = tid & 3;
        const float* srow = w2 + (size_t)e * FF * DIM + (size_t)(f0 + fr) * DIM + d0 + part * 16;
#pragma unroll
        for (int q = 0; q < 4; q++) {
            float4 v = *(const float4*)(srow + q * 4);
            s[fr][part * 16 + q * 4 + 0] = v.x;
            s[fr][part * 16 + q * 4 + 1] = v.y;
            s[fr][part * 16 + q * 4 + 2] = v.z;
            s[fr][part * 16 + q * 4 + 3] = v.w;
        }
    }
    __syncthreads();
    {
        int d = tid >> 2, g = tid & 3;
        float f[16];
#pragma unroll
        for (int k = 0; k < 16; k++) f[k] = s[g * 16 + k][d];
        uint4 h0, l0, h1, l1;
        split8(make_float4(f[0], f[1], f[2], f[3]), make_float4(f[4], f[5], f[6], f[7]), h0, l0);
        split8(make_float4(f[8], f[9], f[10], f[11]), make_float4(f[12], f[13], f[14], f[15]), h1, l1);
        uint4* dst = (uint4*)(g_w2b + ((size_t)(e * DIM + d0 + d) * (FF / 16) + (f0 / 16 + g)) * 32);
        dst[0] = h0; dst[1] = h1; dst[2] = l0; dst[3] = l1;
    }
}

// ---------------- gating ----------------
__global__ void gate_kernel(const float* __restrict__ x, const float* __restrict__ gw,
                            const float* __restrict__ gb) {
    int warp = (blockIdx.x * blockDim.x + threadIdx.x) >> 5;
    int lane = threadIdx.x & 31;
    if (warp >= NTOK) return;
    const float4* xr = (const float4*)(x + (size_t)warp * DIM);
    float4 xv[8];
#pragma unroll
    for (int j = 0; j < 8; j++) xv[j] = xr[j * 32 + lane];
    float mylogit = 0.0f;
    for (int e = 0; e < NEXP; e++) {
        const float4* wr = (const float4*)(gw + (size_t)e * DIM);
        float s = 0.0f;
#pragma unroll
        for (int j = 0; j < 8; j++) {
            float4 wv = wr[j * 32 + lane];
            s += xv[j].x * wv.x + xv[j].y * wv.y + xv[j].z * wv.z + xv[j].w * wv.w;
        }
#pragma unroll
        for (int o = 16; o > 0; o >>= 1) s += __shfl_xor_sync(0xffffffffu, s, o);
        if (lane == e) mylogit = s + gb[e];
    }
    float m0 = mylogit; int i0 = lane;
#pragma unroll
    for (int o = 16; o > 0; o >>= 1) {
        float ov = __shfl_xor_sync(0xffffffffu, m0, o);
        int   oi = __shfl_xor_sync(0xffffffffu, i0, o);
        if (ov > m0 || (ov == m0 && oi < i0)) { m0 = ov; i0 = oi; }
    }
    float v2 = (lane == i0) ? -INFINITY : mylogit;
    float m1 = v2; int i1 = lane;
#pragma unroll
    for (int o = 16; o > 0; o >>= 1) {
        float ov = __shfl_xor_sync(0xffffffffu, m1, o);
        int   oi = __shfl_xor_sync(0xffffffffu, i1, o);
        if (ov > m1 || (ov == m1 && oi < i1)) { m1 = ov; i1 = oi; }
    }
    if (lane == 0) {
        float w0 = 1.0f / (1.0f + expf(m1 - m0));
        g_topi[warp * 2 + 0] = i0;
        g_topi[warp * 2 + 1] = i1;
        g_pair_w[warp * 2 + 0] = w0;
        g_pair_w[warp * 2 + 1] = 1.0f - w0;
    }
}

// ---------------- ordered capacity scan ----------------
__global__ void scan_kernel() {
    int lane = threadIdx.x;
    int cnt = 0;
    for (int i = 0; i < NTOK * TOPK; i++) {
        int e = g_topi[i];
        if (e == lane) {
            int pos = cnt++;
            if (pos < CAP) {
                g_pair_slot[i] = e * CAP + pos;
                g_slot_token[e * CAP + pos] = i >> 1;
            } else {
                g_pair_slot[i] = -1;
            }
        }
    }
    g_nused[lane] = min(cnt, CAP);
}

// ---------------- GEMM compute core: warp tile 64x32, K=16 per iter -------
__device__ __forceinline__ void compute_iter(uint32_t sA, uint32_t sB, int m0, int n0, int lane,
                                             float acc[4][4][4]) {
    uint32_t bh[4][2], bl[4][2];
    const uint32_t brow = (uint32_t)(n0 + (lane & 7)) * ROWB + (((lane >> 3) & 1) * 16);
#pragma unroll
    for (int nj = 0; nj < 4; nj++) {
        uint32_t ba = sB + brow + nj * 8 * ROWB;
        ldsm_x2(bh[nj][0], bh[nj][1], ba);
        ldsm_x2(bl[nj][0], bl[nj][1], ba + 32);
    }
    const uint32_t arow = (uint32_t)(m0 + (lane & 15)) * ROWB + ((lane >> 4) * 16);
#pragma unroll
    for (int mi = 0; mi < 4; mi++) {
        uint32_t ah0, ah1, ah2, ah3, al0, al1, al2, al3;
        uint32_t aa = sA + arow + mi * 16 * ROWB;
        ldsm_x4(ah0, ah1, ah2, ah3, aa);
        ldsm_x4(al0, al1, al2, al3, aa + 32);
#pragma unroll
        for (int nj = 0; nj < 4; nj++)
            mma16816(acc[mi][nj], ah0, ah1, ah2, ah3, bh[nj][0], bh[nj][1]);
#pragma unroll
        for (int nj = 0; nj < 4; nj++)
            mma16816(acc[mi][nj], ah0, ah1, ah2, ah3, bl[nj][0], bl[nj][1]);
#pragma unroll
        for (int nj = 0; nj < 4; nj++)
            mma16816(acc[mi][nj], al0, al1, al2, al3, bh[nj][0], bh[nj][1]);
    }
}

// fill one stage: each thread copies 32B of A row + 32B of B row via cp.async
__device__ __forceinline__ void fill_stage(uint32_t dA, uint32_t dB, const char* sa,
                                           const char* sb) {
    cp16(dA, sa); cp16(dA + 16, sa + 16);
    cp16(dB, sb); cp16(dB + 16, sb + 16);
}

// ---------------- GEMM1: h = gelu(gather(xb) @ w1b^T + b1) ----------------
__global__ __launch_bounds__(256, 2) void gemm1_kernel(const float* __restrict__ b1) {
    const int e = blockIdx.z;
    const int nu = g_nused[e];
    const int row0 = blockIdx.y * 128;
    if (row0 >= nu) return;
    const int col0 = blockIdx.x * 128;

    extern __shared__ __align__(16) char smem[];
    int* tok = (int*)(smem + 2 * STAGES * TILEB);
    const int tid = threadIdx.x;
    const int lane = tid & 31, wid = tid >> 5;
    const int m0 = (wid & 1) * 64, n0 = (wid >> 1) * 32;

    if (tid < 128) {
        int c = row0 + tid;
        tok[tid] = (c < nu) ? g_slot_token[e * CAP + c] : 0;
    }
    __syncthreads();

    const uint32_t sA0 = smem_u32(smem), sB0 = sA0 + STAGES * TILEB;
    const int r = tid >> 1, half = tid & 1;
    const char* asrc = (const char*)g_xb + (size_t)tok[r] * (DIM * 4) + half * 32;
    const char* bsrc = (const char*)g_w1b + ((size_t)e * FF + col0 + r) * (DIM * 4) + half * 32;
    const uint32_t dA = sA0 + r * ROWB + half * 32;
    const uint32_t dB = sB0 + r * ROWB + half * 32;

    float acc[4][4][4];
#pragma unroll
    for (int i = 0; i < 4; i++)
#pragma unroll
        for (int j = 0; j < 4; j++)
#pragma unroll
            for (int q = 0; q < 4; q++) acc[i][j][q] = 0.0f;

    const int NIT = DIM / 16;
#pragma unroll
    for (int s = 0; s < STAGES - 1; s++) {
        fill_stage(dA + s * TILEB, dB + s * TILEB, asrc + s * 64, bsrc + s * 64);
        cp_commit();
    }
    for (int it = 0; it < NIT; ++it) {
        cp_wait<STAGES - 2>();
        __syncthreads();
        const int pf = it + STAGES - 1;
        if (pf < NIT) {
            const int ps = pf & (STAGES - 1);
            fill_stage(dA + ps * TILEB, dB + ps * TILEB, asrc + (size_t)pf * 64,
                       bsrc + (size_t)pf * 64);
        }
        cp_commit();
        const int s = it & (STAGES - 1);
        compute_iter(sA0 + s * TILEB, sB0 + s * TILEB, m0, n0, lane, acc);
    }

    // epilogue: bias + gelu + hi/lo split -> g_h (group layout)
    const int rbase = lane >> 2, cbase = (lane & 3) * 2;
#pragma unroll
    for (int mi = 0; mi < 4; mi++) {
#pragma unroll
        for (int nj = 0; nj < 4; nj++) {
#pragma unroll
            for (int hrow = 0; hrow < 2; hrow++) {
                int rl = m0 + mi * 16 + rbase + hrow * 8;
                int f = col0 + n0 + nj * 8 + cbase;
                float v0 = acc[mi][nj][hrow * 2 + 0] + b1[e * FF + f];
                float v1 = acc[mi][nj][hrow * 2 + 1] + b1[e * FF + f + 1];
                v0 = gelu_tanh(v0); v1 = gelu_tanh(v1);
                __nv_bfloat16 h0 = __float2bfloat16(v0), h1 = __float2bfloat16(v1);
                __nv_bfloat16 l0 = __float2bfloat16(v0 - __bfloat162float(h0));
                __nv_bfloat16 l1 = __float2bfloat16(v1 - __bfloat162float(h1));
                __nv_bfloat16* hr =
                    g_h + (size_t)(e * CAP + row0 + rl) * (FF * 2) + (f >> 4) * 32 + (f & 15);
                *(uint32_t*)hr = pk(h0, h1);
                *(uint32_t*)(hr + 16) = pk(l0, l1);
            }
        }
    }
}

// ---------------- GEMM2: yo = h @ w2b^T + b2 ----------------
__global__ __launch_bounds__(256, 2) void gemm2_kernel(const float* __restrict__ b2) {
    const int e = blockIdx.z;
    const int nu = g_nused[e];
    const int row0 = blockIdx.y * 128;
    if (row0 >= nu) return;
    const int col0 = blockIdx.x * 128;

    extern __shared__ __align__(16) char smem[];
    const int tid = threadIdx.x;
    const int lane = tid & 31, wid = tid >> 5;
    const int m0 = (wid & 1) * 64, n0 = (wid >> 1) * 32;

    const uint32_t sA0 = smem_u32(smem), sB0 = sA0 + STAGES * TILEB;
    const int r = tid >> 1, half = tid & 1;
    const char* asrc = (const char*)g_h + (size_t)(e * CAP + row0 + r) * (FF * 4) + half * 32;
    const char* bsrc = (const char*)g_w2b + ((size_t)e * DIM + col0 + r) * (FF * 4) + half * 32;
    const uint32_t dA = sA0 + r * ROWB + half * 32;
    const uint32_t dB = sB0 + r * ROWB + half * 32;

    float acc[4][4][4];
#pragma unroll
    for (int i = 0; i < 4; i++)
#pragma unroll
        for (int j = 0; j < 4; j++)
#pragma unroll
            for (int q = 0; q < 4; q++) acc[i][j][q] = 0.0f;

    const int NIT = FF / 16;
#pragma unroll
    for (int s = 0; s < STAGES - 1; s++) {
        fill_stage(dA + s * TILEB, dB + s * TILEB, asrc + s * 64, bsrc + s * 64);
        cp_commit();
    }
    for (int it = 0; it < NIT; ++it) {
        cp_wait<STAGES - 2>();
        __syncthreads();
        const int pf = it + STAGES - 1;
        if (pf < NIT) {
            const int ps = pf & (STAGES - 1);
            fill_stage(dA + ps * TILEB, dB + ps * TILEB, asrc + (size_t)pf * 64,
                       bsrc + (size_t)pf * 64);
        }
        cp_commit();
        const int s = it & (STAGES - 1);
        compute_iter(sA0 + s * TILEB, sB0 + s * TILEB, m0, n0, lane, acc);
    }

    const int rbase = lane >> 2, cbase = (lane & 3) * 2;
#pragma unroll
    for (int mi = 0; mi < 4; mi++) {
#pragma unroll
        for (int nj = 0; nj < 4; nj++) {
#pragma unroll
            for (int hrow = 0; hrow < 2; hrow++) {
                int rl = m0 + mi * 16 + rbase + hrow * 8;
                int d = col0 + n0 + nj * 8 + cbase;
                float v0 = acc[mi][nj][hrow * 2 + 0] + b2[e * DIM + d];
                float v1 = acc[mi][nj][hrow * 2 + 1] + b2[e * DIM + d + 1];
                float* dst = g_yo + (size_t)(e * CAP + row0 + rl) * DIM + d;
                *(float2*)dst = make_float2(v0, v1);
            }
        }
    }
}

// ---------------- combine ----------------
__global__ void combine_kernel(float* __restrict__ out) {
    int t = blockIdx.x;
    int d = threadIdx.x * 4;
    int s0 = g_pair_slot[2 * t + 0];
    int s1 = g_pair_slot[2 * t + 1];
    float w0 = g_pair_w[2 * t + 0];
    float w1v = g_pair_w[2 * t + 1];
    float4 r = make_float4(0.f, 0.f, 0.f, 0.f);
    if (s0 >= 0) {
        float4 a = *(const float4*)(g_yo + (size_t)s0 * DIM + d);
        r.x += w0 * a.x; r.y += w0 * a.y; r.z += w0 * a.z; r.w += w0 * a.w;
    }
    if (s1 >= 0) {
        float4 a = *(const float4*)(g_yo + (size_t)s1 * DIM + d);
        r.x += w1v * a.x; r.y += w1v * a.y; r.z += w1v * a.z; r.w += w1v * a.w;
    }
    *(float4*)(out + (size_t)t * DIM + d) = r;
}

// ---------------- launch ----------------
extern "C" void kernel_launch(void* const* d_in, const int* in_sizes, int n_in,
                              void* d_out, int out_size) {
    const float* x      = (const float*)d_in[0];
    const float* gate_w = (const float*)d_in[1];
    const float* gate_b = (const float*)d_in[2];
    const float* w1     = (const float*)d_in[3];
    const float* b1     = (const float*)d_in[4];
    const float* w2     = (const float*)d_in[5];
    const float* b2     = (const float*)d_in[6];
    float* out = (float*)d_out;

    static int configured = 0;
    if (!configured) {
        cudaFuncSetAttribute(gemm1_kernel, cudaFuncAttributeMaxDynamicSharedMemorySize, SMEMB);
        cudaFuncSetAttribute(gemm2_kernel, cudaFuncAttributeMaxDynamicSharedMemorySize, SMEMB);
        configured = 1;
    }

    // operand conversion (fp32 -> bf16 hi/lo groups)
    {
        __nv_bfloat16* xb;  cudaGetSymbolAddress((void**)&xb,  g_xb);
        __nv_bfloat16* w1b; cudaGetSymbolAddress((void**)&w1b, g_w1b);
        int ngx  = NTOK * DIM / 16;
        int ngw1 = (int)((size_t)NEXP * FF * DIM / 16);
        conv_split_kernel<<<(ngx + 255) / 256, 256>>>(x, xb, ngx);
        conv_split_kernel<<<(ngw1 + 255) / 256, 256>>>(w1, w1b, ngw1);
        conv_w2t_kernel<<<dim3(FF / 64, DIM / 64, NEXP), 256>>>(w2);
    }

    gate_kernel<<<NTOK / 8, 256>>>(x, gate_w, gate_b);
    scan_kernel<<<1, 32>>>();
    gemm1_kernel<<<dim3(FF / 128, CAP / 128, NEXP), 256, SMEMB>>>(b1);
    gemm2_kernel<<<dim3(DIM / 128, CAP / 128, NEXP), 256, SMEMB>>>(b2);
    combine_kernel<<<NTOK, 256>>>(out);
}

// round 5
// speedup vs baseline: 3.0639x; 1.1757x over previous
#include <cuda_runtime.h>
#include <cuda_bf16.h>
#include <math.h>
#include <stdint.h>

#define NTOK 4096
#define DIM  1024
#define FF   4096
#define NEXP 32
#define TOPK 2
#define CAP  512

__device__ float g_w2t[(size_t)NEXP * DIM * FF];   // 512 MB: w2 transposed [E][D][F]
__device__ float g_h  [(size_t)NEXP * CAP * FF];   // 256 MB: gelu(fc1), k-major for GEMM2
__device__ float g_yo [(size_t)NEXP * CAP * DIM];  // 64 MB
__device__ int   g_slot_token[NEXP * CAP];
__device__ int   g_pair_slot[NTOK * TOPK];
__device__ float g_pair_w[NTOK * TOPK];
__device__ int   g_topi[NTOK * TOPK];
__device__ int   g_nused[NEXP];

// ---------------- helpers ----------------
__device__ __forceinline__ uint32_t smem_u32(const void* p) {
    uint32_t a;
    asm("{ .reg .u64 t; cvta.to.shared.u64 t, %1; cvt.u32.u64 %0, t; }" : "=r"(a) : "l"(p));
    return a;
}
__device__ __forceinline__ void cp16(uint32_t d, const void* s) {
    asm volatile("cp.async.cg.shared.global [%0], [%1], 16;" :: "r"(d), "l"(s));
}
__device__ __forceinline__ void cp_commit() { asm volatile("cp.async.commit_group;"); }
template <int N>
__device__ __forceinline__ void cp_wait() { asm volatile("cp.async.wait_group %0;" :: "n"(N)); }

__device__ __forceinline__ void ldsm_x4(uint32_t& r0, uint32_t& r1, uint32_t& r2, uint32_t& r3,
                                        uint32_t addr) {
    asm volatile("ldmatrix.sync.aligned.m8n8.x4.shared.b16 {%0,%1,%2,%3}, [%4];"
                 : "=r"(r0), "=r"(r1), "=r"(r2), "=r"(r3) : "r"(addr));
}
__device__ __forceinline__ void ldsm_x2(uint32_t& r0, uint32_t& r1, uint32_t addr) {
    asm volatile("ldmatrix.sync.aligned.m8n8.x2.shared.b16 {%0,%1}, [%2];"
                 : "=r"(r0), "=r"(r1) : "r"(addr));
}
__device__ __forceinline__ uint32_t f2tf(uint32_t x) {
    uint32_t r;
    asm("cvt.rna.tf32.f32 %0, %1;" : "=r"(r) : "f"(__uint_as_float(x)));
    return r;
}
__device__ __forceinline__ void mma_tf32(float* c, uint32_t a0, uint32_t a1, uint32_t a2,
                                         uint32_t a3, uint32_t b0, uint32_t b1) {
    asm volatile(
        "mma.sync.aligned.m16n8k8.row.col.f32.tf32.tf32.f32 "
        "{%0,%1,%2,%3}, {%4,%5,%6,%7}, {%8,%9}, {%0,%1,%2,%3};"
        : "+f"(c[0]), "+f"(c[1]), "+f"(c[2]), "+f"(c[3])
        : "r"(a0), "r"(a1), "r"(a2), "r"(a3), "r"(b0), "r"(b1));
}
__device__ __forceinline__ float gelu_tanh(float v) {
    float c = v + 0.044715f * v * v * v;
    return 0.5f * v * (1.0f + tanhf(0.7978845608028654f * c));
}

#define ROWB   80          // smem row stride: 64B (16 fp32 = K16) + 16B pad
#define TILEB  (128 * ROWB)
#define STAGES 4
#define SMEMB  (2 * STAGES * TILEB + 512)

// ---------------- w2 transpose: [E][F][D] -> [E][D][F] fp32 ----------------
__global__ __launch_bounds__(256) void w2t_kernel(const float* __restrict__ w2) {
    const int e = blockIdx.z;
    const int f0 = blockIdx.x * 64;
    const int d0 = blockIdx.y * 64;
    __shared__ float s[64][65];
    const int tid = threadIdx.x;
    {
        int fr = tid >> 2, part = tid & 3;
        const float* srow = w2 + (size_t)e * FF * DIM + (size_t)(f0 + fr) * DIM + d0 + part * 16;
#pragma unroll
        for (int q = 0; q < 4; q++) {
            float4 v = *(const float4*)(srow + q * 4);
            s[fr][part * 16 + q * 4 + 0] = v.x;
            s[fr][part * 16 + q * 4 + 1] = v.y;
            s[fr][part * 16 + q * 4 + 2] = v.z;
            s[fr][part * 16 + q * 4 + 3] = v.w;
        }
    }
    __syncthreads();
    {
        int d = tid >> 2, g = tid & 3;
        float* dst = g_w2t + ((size_t)e * DIM + d0 + d) * FF + f0 + g * 16;
#pragma unroll
        for (int q = 0; q < 4; q++) {
            float4 v = make_float4(s[g * 16 + q * 4 + 0][d], s[g * 16 + q * 4 + 1][d],
                                   s[g * 16 + q * 4 + 2][d], s[g * 16 + q * 4 + 3][d]);
            *(float4*)(dst + q * 4) = v;
        }
    }
}

// ---------------- gating ----------------
__global__ void gate_kernel(const float* __restrict__ x, const float* __restrict__ gw,
                            const float* __restrict__ gb) {
    int warp = (blockIdx.x * blockDim.x + threadIdx.x) >> 5;
    int lane = threadIdx.x & 31;
    if (warp >= NTOK) return;
    const float4* xr = (const float4*)(x + (size_t)warp * DIM);
    float4 xv[8];
#pragma unroll
    for (int j = 0; j < 8; j++) xv[j] = xr[j * 32 + lane];
    float mylogit = 0.0f;
    for (int e = 0; e < NEXP; e++) {
        const float4* wr = (const float4*)(gw + (size_t)e * DIM);
        float s = 0.0f;
#pragma unroll
        for (int j = 0; j < 8; j++) {
            float4 wv = wr[j * 32 + lane];
            s += xv[j].x * wv.x + xv[j].y * wv.y + xv[j].z * wv.z + xv[j].w * wv.w;
        }
#pragma unroll
        for (int o = 16; o > 0; o >>= 1) s += __shfl_xor_sync(0xffffffffu, s, o);
        if (lane == e) mylogit = s + gb[e];
    }
    float m0 = mylogit; int i0 = lane;
#pragma unroll
    for (int o = 16; o > 0; o >>= 1) {
        float ov = __shfl_xor_sync(0xffffffffu, m0, o);
        int   oi = __shfl_xor_sync(0xffffffffu, i0, o);
        if (ov > m0 || (ov == m0 && oi < i0)) { m0 = ov; i0 = oi; }
    }
    float v2 = (lane == i0) ? -INFINITY : mylogit;
    float m1 = v2; int i1 = lane;
#pragma unroll
    for (int o = 16; o > 0; o >>= 1) {
        float ov = __shfl_xor_sync(0xffffffffu, m1, o);
        int   oi = __shfl_xor_sync(0xffffffffu, i1, o);
        if (ov > m1 || (ov == m1 && oi < i1)) { m1 = ov; i1 = oi; }
    }
    if (lane == 0) {
        float w0 = 1.0f / (1.0f + expf(m1 - m0));
        g_topi[warp * 2 + 0] = i0;
        g_topi[warp * 2 + 1] = i1;
        g_pair_w[warp * 2 + 0] = w0;
        g_pair_w[warp * 2 + 1] = 1.0f - w0;
    }
}

// ---------------- ordered capacity scan (coalesced chunks + shfl) ----------
__global__ void scan_kernel() {
    int lane = threadIdx.x;
    int cnt = 0;
    for (int base = 0; base < NTOK * TOPK; base += 32) {
        int v = g_topi[base + lane];
#pragma unroll
        for (int j = 0; j < 32; j++) {
            int ev = __shfl_sync(0xffffffffu, v, j);
            if (ev == lane) {
                int pos = cnt++;
                int i = base + j;
                if (pos < CAP) {
                    g_pair_slot[i] = lane * CAP + pos;
                    g_slot_token[lane * CAP + pos] = i >> 1;
                } else {
                    g_pair_slot[i] = -1;
                }
            }
        }
    }
    g_nused[lane] = min(cnt, CAP);
}

// ---------------- tf32 compute core: warp tile 64x32, K=16 per iter --------
__device__ __forceinline__ void compute_iter(uint32_t sA, uint32_t sB, int m0, int n0, int lane,
                                             float acc[4][4][4]) {
    uint32_t b[4][2][2];
    const uint32_t brow = (uint32_t)(n0 + (lane & 7)) * ROWB + (((lane >> 3) & 1) * 16);
#pragma unroll
    for (int nj = 0; nj < 4; nj++) {
        uint32_t ba = sB + brow + nj * 8 * ROWB;
        ldsm_x2(b[nj][0][0], b[nj][0][1], ba);        // k0-7
        ldsm_x2(b[nj][1][0], b[nj][1][1], ba + 32);   // k8-15
    }
#pragma unroll
    for (int nj = 0; nj < 4; nj++)
#pragma unroll
        for (int ks = 0; ks < 2; ks++) {
            b[nj][ks][0] = f2tf(b[nj][ks][0]);
            b[nj][ks][1] = f2tf(b[nj][ks][1]);
        }
    const uint32_t arow = (uint32_t)(m0 + (lane & 15)) * ROWB + ((lane >> 4) * 16);
#pragma unroll
    for (int mi = 0; mi < 4; mi++) {
        uint32_t a0[4], a1[4];
        uint32_t aa = sA + arow + mi * 16 * ROWB;
        ldsm_x4(a0[0], a0[1], a0[2], a0[3], aa);        // k0-7
        ldsm_x4(a1[0], a1[1], a1[2], a1[3], aa + 32);   // k8-15
#pragma unroll
        for (int q = 0; q < 4; q++) { a0[q] = f2tf(a0[q]); a1[q] = f2tf(a1[q]); }
#pragma unroll
        for (int nj = 0; nj < 4; nj++)
            mma_tf32(acc[mi][nj], a0[0], a0[1], a0[2], a0[3], b[nj][0][0], b[nj][0][1]);
#pragma unroll
        for (int nj = 0; nj < 4; nj++)
            mma_tf32(acc[mi][nj], a1[0], a1[1], a1[2], a1[3], b[nj][1][0], b[nj][1][1]);
    }
}

__device__ __forceinline__ void fill_stage(uint32_t dA, uint32_t dB, const char* sa,
                                           const char* sb) {
    cp16(dA, sa); cp16(dA + 16, sa + 16);
    cp16(dB, sb); cp16(dB + 16, sb + 16);
}

// ---------------- GEMM1: h = gelu(gather(x) @ w1[e]^T + b1) ----------------
__global__ __launch_bounds__(256, 2) void gemm1_kernel(const float* __restrict__ x,
                                                       const float* __restrict__ w1,
                                                       const float* __restrict__ b1) {
    const int e = blockIdx.z;
    const int nu = g_nused[e];
    const int row0 = blockIdx.y * 128;
    if (row0 >= nu) return;
    const int col0 = blockIdx.x * 128;

    extern __shared__ __align__(16) char smem[];
    int* tok = (int*)(smem + 2 * STAGES * TILEB);
    const int tid = threadIdx.x;
    const int lane = tid & 31, wid = tid >> 5;
    const int m0 = (wid & 1) * 64, n0 = (wid >> 1) * 32;

    if (tid < 128) {
        int c = row0 + tid;
        tok[tid] = (c < nu) ? g_slot_token[e * CAP + c] : 0;
    }
    __syncthreads();

    const uint32_t sA0 = smem_u32(smem), sB0 = sA0 + STAGES * TILEB;
    const int r = tid >> 1, half = tid & 1;
    const char* asrc = (const char*)(x + (size_t)tok[r] * DIM) + half * 32;
    const char* bsrc = (const char*)(w1 + ((size_t)e * FF + col0 + r) * DIM) + half * 32;
    const uint32_t dA = sA0 + r * ROWB + half * 32;
    const uint32_t dB = sB0 + r * ROWB + half * 32;

    float acc[4][4][4];
#pragma unroll
    for (int i = 0; i < 4; i++)
#pragma unroll
        for (int j = 0; j < 4; j++)
#pragma unroll
            for (int q = 0; q < 4; q++) acc[i][j][q] = 0.0f;

    const int NIT = DIM / 16;
#pragma unroll
    for (int s = 0; s < STAGES - 1; s++) {
        fill_stage(dA + s * TILEB, dB + s * TILEB, asrc + s * 64, bsrc + s * 64);
        cp_commit();
    }
    for (int it = 0; it < NIT; ++it) {
        cp_wait<STAGES - 2>();
        __syncthreads();
        const int pf = it + STAGES - 1;
        if (pf < NIT) {
            const int ps = pf & (STAGES - 1);
            fill_stage(dA + ps * TILEB, dB + ps * TILEB, asrc + (size_t)pf * 64,
                       bsrc + (size_t)pf * 64);
        }
        cp_commit();
        const int s = it & (STAGES - 1);
        compute_iter(sA0 + s * TILEB, sB0 + s * TILEB, m0, n0, lane, acc);
    }

    // epilogue: bias + gelu -> g_h (fp32, k-major for GEMM2)
    const int rbase = lane >> 2, cbase = (lane & 3) * 2;
#pragma unroll
    for (int mi = 0; mi < 4; mi++) {
#pragma unroll
        for (int nj = 0; nj < 4; nj++) {
#pragma unroll
            for (int hrow = 0; hrow < 2; hrow++) {
                int rl = m0 + mi * 16 + rbase + hrow * 8;
                int f = col0 + n0 + nj * 8 + cbase;
                float v0 = acc[mi][nj][hrow * 2 + 0] + b1[e * FF + f];
                float v1 = acc[mi][nj][hrow * 2 + 1] + b1[e * FF + f + 1];
                v0 = gelu_tanh(v0); v1 = gelu_tanh(v1);
                float* hr = g_h + (size_t)(e * CAP + row0 + rl) * FF + f;
                *(float2*)hr = make_float2(v0, v1);
            }
        }
    }
}

// ---------------- GEMM2: yo = h @ w2t[e]^T + b2 ----------------
__global__ __launch_bounds__(256, 2) void gemm2_kernel(const float* __restrict__ b2) {
    const int e = blockIdx.z;
    const int nu = g_nused[e];
    const int row0 = blockIdx.y * 128;
    if (row0 >= nu) return;
    const int col0 = blockIdx.x * 128;

    extern __shared__ __align__(16) char smem[];
    const int tid = threadIdx.x;
    const int lane = tid & 31, wid = tid >> 5;
    const int m0 = (wid & 1) * 64, n0 = (wid >> 1) * 32;

    const uint32_t sA0 = smem_u32(smem), sB0 = sA0 + STAGES * TILEB;
    const int r = tid >> 1, half = tid & 1;
    const char* asrc = (const char*)(g_h + (size_t)(e * CAP + row0 + r) * FF) + half * 32;
    const char* bsrc = (const char*)(g_w2t + ((size_t)e * DIM + col0 + r) * FF) + half * 32;
    const uint32_t dA = sA0 + r * ROWB + half * 32;
    const uint32_t dB = sB0 + r * ROWB + half * 32;

    float acc[4][4][4];
#pragma unroll
    for (int i = 0; i < 4; i++)
#pragma unroll
        for (int j = 0; j < 4; j++)
#pragma unroll
            for (int q = 0; q < 4; q++) acc[i][j][q] = 0.0f;

    const int NIT = FF / 16;
#pragma unroll
    for (int s = 0; s < STAGES - 1; s++) {
        fill_stage(dA + s * TILEB, dB + s * TILEB, asrc + s * 64, bsrc + s * 64);
        cp_commit();
    }
    for (int it = 0; it < NIT; ++it) {
        cp_wait<STAGES - 2>();
        __syncthreads();
        const int pf = it + STAGES - 1;
        if (pf < NIT) {
            const int ps = pf & (STAGES - 1);
            fill_stage(dA + ps * TILEB, dB + ps * TILEB, asrc + (size_t)pf * 64,
                       bsrc + (size_t)pf * 64);
        }
        cp_commit();
        const int s = it & (STAGES - 1);
        compute_iter(sA0 + s * TILEB, sB0 + s * TILEB, m0, n0, lane, acc);
    }

    const int rbase = lane >> 2, cbase = (lane & 3) * 2;
#pragma unroll
    for (int mi = 0; mi < 4; mi++) {
#pragma unroll
        for (int nj = 0; nj < 4; nj++) {
#pragma unroll
            for (int hrow = 0; hrow < 2; hrow++) {
                int rl = m0 + mi * 16 + rbase + hrow * 8;
                int d = col0 + n0 + nj * 8 + cbase;
                float v0 = acc[mi][nj][hrow * 2 + 0] + b2[e * DIM + d];
                float v1 = acc[mi][nj][hrow * 2 + 1] + b2[e * DIM + d + 1];
                float* dst = g_yo + (size_t)(e * CAP + row0 + rl) * DIM + d;
                *(float2*)dst = make_float2(v0, v1);
            }
        }
    }
}

// ---------------- combine ----------------
__global__ void combine_kernel(float* __restrict__ out) {
    int t = blockIdx.x;
    int d = threadIdx.x * 4;
    int s0 = g_pair_slot[2 * t + 0];
    int s1 = g_pair_slot[2 * t + 1];
    float w0 = g_pair_w[2 * t + 0];
    float w1v = g_pair_w[2 * t + 1];
    float4 r = make_float4(0.f, 0.f, 0.f, 0.f);
    if (s0 >= 0) {
        float4 a = *(const float4*)(g_yo + (size_t)s0 * DIM + d);
        r.x += w0 * a.x; r.y += w0 * a.y; r.z += w0 * a.z; r.w += w0 * a.w;
    }
    if (s1 >= 0) {
        float4 a = *(const float4*)(g_yo + (size_t)s1 * DIM + d);
        r.x += w1v * a.x; r.y += w1v * a.y; r.z += w1v * a.z; r.w += w1v * a.w;
    }
    *(float4*)(out + (size_t)t * DIM + d) = r;
}

// ---------------- launch ----------------
extern "C" void kernel_launch(void* const* d_in, const int* in_sizes, int n_in,
                              void* d_out, int out_size) {
    const float* x      = (const float*)d_in[0];
    const float* gate_w = (const float*)d_in[1];
    const float* gate_b = (const float*)d_in[2];
    const float* w1     = (const float*)d_in[3];
    const float* b1     = (const float*)d_in[4];
    const float* w2     = (const float*)d_in[5];
    const float* b2     = (const float*)d_in[6];
    float* out = (float*)d_out;

    static int configured = 0;
    if (!configured) {
        cudaFuncSetAttribute(gemm1_kernel, cudaFuncAttributeMaxDynamicSharedMemorySize, SMEMB);
        cudaFuncSetAttribute(gemm2_kernel, cudaFuncAttributeMaxDynamicSharedMemorySize, SMEMB);
        configured = 1;
    }

    gate_kernel<<<NTOK / 8, 256>>>(x, gate_w, gate_b);
    scan_kernel<<<1, 32>>>();
    w2t_kernel<<<dim3(FF / 64, DIM / 64, NEXP), 256>>>(w2);
    gemm1_kernel<<<dim3(FF / 128, CAP / 128, NEXP), 256, SMEMB>>>(x, w1, b1);
    gemm2_kernel<<<dim3(DIM / 128, CAP / 128, NEXP), 256, SMEMB>>>(b2);
    combine_kernel<<<NTOK, 256>>>(out);
}